// round 17
// baseline (speedup 1.0000x reference)
#include <cuda_runtime.h>

#define N_NODES 50000
#define IN_F    128
#define OUT_F   64
#define HEADS   2
#define ALPHA   0.2f

#define XS_STRIDE 132
#define TILE_M    64
#define NBLK1     888     // front kernel: 6 CTAs x 148 SMs (<=42 regs)
#define NBLK2     296     // gemm kernel: 2 CTAs x 148 SMs

__device__ float  g_v[512];          // [which(i/j)][head][128]
__device__ float2 g_si[N_NODES];
__device__ float2 g_sj[N_NODES];
__device__ float2 g_c[N_NODES];      // per-node sum of exp(e) per head
__device__ float  g_Z[2];            // global softmax denominator per head
__device__ unsigned g_wpack[16384];  // W in tf32 MMA-fragment order (64KB)
__device__ unsigned g_barrier_ctr = 0;

__device__ __forceinline__ unsigned f2tf32(float f) {
    unsigned u;
    asm("cvt.rna.tf32.f32 %0, %1;" : "=r"(u) : "f"(f));
    return u;
}

// software grid barrier; monotonic counter -> safe across graph replays
__device__ __forceinline__ void grid_bar(unsigned nblk) {
    __syncthreads();
    if (threadIdx.x == 0) {
        unsigned old;
        asm volatile("atom.release.gpu.global.add.u32 %0, [%1], 1;"
                     : "=r"(old) : "l"(&g_barrier_ctr) : "memory");
        unsigned target = old - (old % nblk) + nblk;
        unsigned cur;
        do {
            asm volatile("ld.acquire.gpu.global.u32 %0, [%1];"
                         : "=r"(cur) : "l"(&g_barrier_ctr) : "memory");
        } while (cur < target);
    }
    __syncthreads();
}

__device__ __forceinline__ float2 edge_w(float2 si, float2 sj) {
    float e0 = si.x + sj.x;
    float e1 = si.y + sj.y;
    e0 = e0 > 0.f ? e0 : ALPHA * e0;
    e1 = e1 > 0.f ? e1 : ALPHA * e1;
    return make_float2(__expf(e0), __expf(e1));
}

// ---------------------------------------------------------------------------
// K1: prep | bar | node_s | bar | edge   -- low-reg, 6 CTAs/SM (48 warps/SM)
__global__ void __launch_bounds__(256, 6) gat_front_kernel(
        const float* __restrict__ x, const float* __restrict__ W,
        const float* __restrict__ a, const int* __restrict__ ei,
        int N, int E) {
    __shared__ float vsm[512];
    __shared__ float s0[8], s1[8];

    int tid = threadIdx.x;
    int bid = blockIdx.x;
    int warp = tid >> 5, lane = tid & 31;

    // ===== Phase A: prep (wpack + v + zero Z); only blocks < 64 have work =====
    {
        int idx = bid * 256 + tid;
        if (idx < 16384) {
            int q    = idx & 3;
            int ln   = (idx >> 2) & 31;
            int ks   = (idx >> 7) & 15;
            int w    = (idx >> 11) & 7;
            int g = ln >> 2, t = ln & 3;
            int ni  = q >> 1;
            int sel = q & 1;
            int c = w * 16 + ni * 8 + g;
            int k = ks * 8 + t + sel * 4;
            int h = c >> 6, o = c & 63;
            g_wpack[idx] = f2tf32(W[((size_t)h * 128 + k) * 64 + o]);
        }
        if (idx < 2) g_Z[idx] = 0.0f;
        if (idx < 512) {
            int which = idx >> 8;
            int h     = (idx >> 7) & 1;
            int i     = idx & 127;
            const float* wrow = W + h * (IN_F * OUT_F) + i * OUT_F;
            const float* av   = a + h * (2 * OUT_F) + which * OUT_F;
            float s = 0.f;
#pragma unroll 16
            for (int o = 0; o < OUT_F; o++) s += wrow[o] * av[o];
            g_v[which * 256 + h * 128 + i] = s;
        }
    }
    grid_bar(NBLK1);

    // ===== Phase B: per-node scores (warp per node, grid-stride) =====
    {
        vsm[tid]       = g_v[tid];
        vsm[tid + 256] = g_v[tid + 256];
        __syncthreads();

        const float4* v4 = (const float4*)vsm;
        float4 vi0 = v4[lane];
        float4 vi1 = v4[32 + lane];
        float4 vj0 = v4[64 + lane];
        float4 vj1 = v4[96 + lane];

        for (int n = bid * 8 + warp; n < N; n += NBLK1 * 8) {
            float4 xv = ((const float4*)x)[(size_t)n * 32 + lane];
            float si0 = xv.x*vi0.x + xv.y*vi0.y + xv.z*vi0.z + xv.w*vi0.w;
            float si1 = xv.x*vi1.x + xv.y*vi1.y + xv.z*vi1.z + xv.w*vi1.w;
            float sj0 = xv.x*vj0.x + xv.y*vj0.y + xv.z*vj0.z + xv.w*vj0.w;
            float sj1 = xv.x*vj1.x + xv.y*vj1.y + xv.z*vj1.z + xv.w*vj1.w;
#pragma unroll
            for (int off = 16; off; off >>= 1) {
                si0 += __shfl_xor_sync(0xffffffffu, si0, off);
                si1 += __shfl_xor_sync(0xffffffffu, si1, off);
                sj0 += __shfl_xor_sync(0xffffffffu, sj0, off);
                sj1 += __shfl_xor_sync(0xffffffffu, sj1, off);
            }
            if (lane == 0) {
                g_si[n] = make_float2(si0, si1);
                g_sj[n] = make_float2(sj0, sj1);
                g_c[n]  = make_float2(0.f, 0.f);
            }
        }
    }
    grid_bar(NBLK1);

    // ===== Phase C: edges (4 per thread, MLP-batched gathers; fused Z) =====
    {
        float z0 = 0.f, z1 = 0.f;
        int nQuads = (E + 3) >> 2;
        for (int k4 = bid * 256 + tid; k4 < nQuads; k4 += NBLK1 * 256) {
            int k = k4 * 4;
            if (k + 3 < E) {
                int4 s4 = *(const int4*)(ei + k);
                int4 d4 = *(const int4*)(ei + E + k);
                float2 si0 = __ldg(&g_si[s4.x]);
                float2 si1 = __ldg(&g_si[s4.y]);
                float2 si2 = __ldg(&g_si[s4.z]);
                float2 si3 = __ldg(&g_si[s4.w]);
                float2 sj0 = __ldg(&g_sj[d4.x]);
                float2 sj1 = __ldg(&g_sj[d4.y]);
                float2 sj2 = __ldg(&g_sj[d4.z]);
                float2 sj3 = __ldg(&g_sj[d4.w]);
                float2 w0 = edge_w(si0, sj0);
                float2 w1 = edge_w(si1, sj1);
                float2 w2 = edge_w(si2, sj2);
                float2 w3 = edge_w(si3, sj3);
                asm volatile("red.global.add.v2.f32 [%0], {%1, %2};"
                             :: "l"(&g_c[d4.x]), "f"(w0.x), "f"(w0.y) : "memory");
                asm volatile("red.global.add.v2.f32 [%0], {%1, %2};"
                             :: "l"(&g_c[d4.y]), "f"(w1.x), "f"(w1.y) : "memory");
                asm volatile("red.global.add.v2.f32 [%0], {%1, %2};"
                             :: "l"(&g_c[d4.z]), "f"(w2.x), "f"(w2.y) : "memory");
                asm volatile("red.global.add.v2.f32 [%0], {%1, %2};"
                             :: "l"(&g_c[d4.w]), "f"(w3.x), "f"(w3.y) : "memory");
                z0 += w0.x + w1.x + w2.x + w3.x;
                z1 += w0.y + w1.y + w2.y + w3.y;
            } else {
                for (; k < E; k++) {
                    int src = __ldg(ei + k);
                    int dst = __ldg(ei + E + k);
                    float2 w = edge_w(g_si[src], g_sj[dst]);
                    asm volatile("red.global.add.v2.f32 [%0], {%1, %2};"
                                 :: "l"(&g_c[dst]), "f"(w.x), "f"(w.y) : "memory");
                    z0 += w.x;
                    z1 += w.y;
                }
            }
        }
#pragma unroll
        for (int off = 16; off; off >>= 1) {
            z0 += __shfl_xor_sync(0xffffffffu, z0, off);
            z1 += __shfl_xor_sync(0xffffffffu, z1, off);
        }
        if (lane == 0) { s0[warp] = z0; s1[warp] = z1; }
        __syncthreads();
        if (tid == 0) {
            float t0 = 0.f, t1 = 0.f;
#pragma unroll
            for (int w = 0; w < 8; w++) { t0 += s0[w]; t1 += s1[w]; }
            asm volatile("red.global.add.v2.f32 [%0], {%1, %2};"
                         :: "l"(g_Z), "f"(t0), "f"(t1) : "memory");
        }
    }
}

// ---------------------------------------------------------------------------
// K2: gemm (tf32 mma.sync, B in registers, persistent, CVT at staging)
__device__ __forceinline__ void mma_tf32(float* d,
                                         unsigned a0, unsigned a1, unsigned a2, unsigned a3,
                                         unsigned b0, unsigned b1) {
    asm volatile("mma.sync.aligned.m16n8k8.row.col.f32.tf32.tf32.f32 "
                 "{%0,%1,%2,%3}, {%4,%5,%6,%7}, {%8,%9}, {%0,%1,%2,%3};"
                 : "+f"(d[0]), "+f"(d[1]), "+f"(d[2]), "+f"(d[3])
                 : "r"(a0), "r"(a1), "r"(a2), "r"(a3), "r"(b0), "r"(b1));
}

__global__ void __launch_bounds__(256, 2) out_gemm_kernel(const float* __restrict__ x,
                                                          float* __restrict__ out,
                                                          int N, int numTiles) {
    __shared__ unsigned xs[TILE_M * XS_STRIDE];   // tf32 x tile

    int tid = threadIdx.x;
    int wn   = tid >> 5;            // warp 0..7 : 16-col band
    int lane = tid & 31;
    int g    = lane >> 2;
    int t    = lane & 3;
    int head = wn >> 2;
    float rz = 1.0f / g_Z[head];

    const float4* x4 = (const float4*)x;

    for (int tile = blockIdx.x; tile < numTiles; tile += NBLK2) {
        int n0 = tile * TILE_M;
        __syncthreads();

        // stage x tile, tf32-converted AT STAGING (mainloop has zero CVTs)
#pragma unroll
        for (int it = 0; it < 8; it++) {
            int idx = tid + it * 256;
            int r   = idx >> 5;
            int k4  = idx & 31;
            int n   = n0 + r;
            float4 v = make_float4(0.f, 0.f, 0.f, 0.f);
            if (n < N) v = x4[(size_t)n * 32 + k4];
            *(uint4*)&xs[r * XS_STRIDE + k4 * 4] =
                make_uint4(f2tf32(v.x), f2tf32(v.y), f2tf32(v.z), f2tf32(v.w));
        }
        __syncthreads();

        float acc[4][2][4];
#pragma unroll
        for (int mi = 0; mi < 4; mi++)
#pragma unroll
            for (int ni = 0; ni < 2; ni++)
#pragma unroll
                for (int q = 0; q < 4; q++) acc[mi][ni][q] = 0.f;

#pragma unroll
        for (int half = 0; half < 2; half++) {
            uint4 bh[8];
            const uint4* wp = (const uint4*)g_wpack + (wn * 16 + half * 8) * 32 + lane;
#pragma unroll
            for (int k2 = 0; k2 < 8; k2++) bh[k2] = wp[k2 * 32];

#pragma unroll
            for (int k2 = 0; k2 < 8; k2++) {
                int k0 = (half * 8 + k2) * 8;
                unsigned av[4][4];
#pragma unroll
                for (int mi = 0; mi < 4; mi++) {
                    int r0 = mi * 16;
                    av[mi][0] = xs[(r0 + g)     * XS_STRIDE + k0 + t];
                    av[mi][1] = xs[(r0 + g + 8) * XS_STRIDE + k0 + t];
                    av[mi][2] = xs[(r0 + g)     * XS_STRIDE + k0 + t + 4];
                    av[mi][3] = xs[(r0 + g + 8) * XS_STRIDE + k0 + t + 4];
                }
#pragma unroll
                for (int mi = 0; mi < 4; mi++) {
                    mma_tf32(acc[mi][0], av[mi][0], av[mi][1], av[mi][2], av[mi][3],
                             bh[k2].x, bh[k2].y);
                    mma_tf32(acc[mi][1], av[mi][0], av[mi][1], av[mi][2], av[mi][3],
                             bh[k2].z, bh[k2].w);
                }
            }
        }

        // epilogue: scale by c[n,head]/Z_head
#pragma unroll
        for (int mi = 0; mi < 4; mi++) {
            int r0 = n0 + mi * 16 + g;
            int r1 = r0 + 8;
            float scl0 = 0.f, scl1 = 0.f;
            if (r0 < N) {
                float2 cc = g_c[r0];
                scl0 = (head ? cc.y : cc.x) * rz;
            }
            if (r1 < N) {
                float2 cc = g_c[r1];
                scl1 = (head ? cc.y : cc.x) * rz;
            }
#pragma unroll
            for (int ni = 0; ni < 2; ni++) {
                int col = wn * 16 + ni * 8 + 2 * t;
                if (r0 < N)
                    *(float2*)&out[(size_t)r0 * 128 + col] =
                        make_float2(acc[mi][ni][0] * scl0, acc[mi][ni][1] * scl0);
                if (r1 < N)
                    *(float2*)&out[(size_t)r1 * 128 + col] =
                        make_float2(acc[mi][ni][2] * scl1, acc[mi][ni][3] * scl1);
            }
        }
    }
}

// ---------------------------------------------------------------------------
extern "C" void kernel_launch(void* const* d_in, const int* in_sizes, int n_in,
                              void* d_out, int out_size) {
    const float* x  = (const float*)d_in[0];
    const float* W  = (const float*)d_in[1];
    const float* a  = (const float*)d_in[2];
    const int*   ei = (const int*)d_in[3];
    float* out = (float*)d_out;

    int N = in_sizes[0] / IN_F;
    if (N > N_NODES) N = N_NODES;
    int E = in_sizes[3] / 2;
    int numTiles = (N + TILE_M - 1) / TILE_M;

    gat_front_kernel<<<NBLK1, 256>>>(x, W, a, ei, N, E);
    out_gemm_kernel<<<NBLK2, 256>>>(x, out, N, numTiles);
}